// round 1
// baseline (speedup 1.0000x reference)
#include <cuda_runtime.h>
#include <cuda_bf16.h>
#include <math.h>

// Problem constants
#define BB 64
#define PP 196
#define DD 768
#define CC 201
#define KP 5
#define NCLS 200
#define NN (BB*PP)        // 12544
#define JJ (CC*KP)        // 1005

// Output layout (float32, concatenated in reference return order)
#define OFF_LOGITS 0
#define SZ_LOGITS  (NN*JJ)                 // 12,606,720
#define OFF_IMG    (OFF_LOGITS + SZ_LOGITS)
#define SZ_IMG     (BB*JJ)                 // 64,320
#define OFF_CLS    (OFF_IMG + SZ_IMG)
#define SZ_CLS     (BB*NCLS)               // 12,800
#define OFF_ASGN   (OFF_CLS + SZ_CLS)
#define SZ_ASGN    (NN)                    // 12,544
#define OFF_PNEW   (OFF_ASGN + SZ_ASGN)
#define SZ_PNEW    (CC*KP*DD)              // 771,840

// Device scratch (no cudaMalloc allowed)
__device__ float g_pt[NN*DD];      // normalized patch tokens
__device__ float g_rpt[NN*DD];     // normalized raw patch tokens
__device__ float g_pn[JJ*DD];      // normalized prototypes (C*K rows)
__device__ float g_sw[NCLS*KP];    // softmax(sa_weights)*K

// ---------------------------------------------------------------------------
// Row L2 normalization: rows 0..NN-1 -> pt, NN..2NN-1 -> rpt, rest -> protos
// ---------------------------------------------------------------------------
__global__ void norm_kernel(const float* __restrict__ pt,
                            const float* __restrict__ rpt,
                            const float* __restrict__ proto) {
    int r = blockIdx.x;
    const float* src; float* dst;
    if (r < NN)            { src = pt   + (size_t)r*DD;          dst = g_pt  + (size_t)r*DD; }
    else if (r < 2*NN)     { src = rpt  + (size_t)(r-NN)*DD;     dst = g_rpt + (size_t)(r-NN)*DD; }
    else                   { src = proto+ (size_t)(r-2*NN)*DD;   dst = g_pn  + (size_t)(r-2*NN)*DD; }
    int tid = threadIdx.x;
    float s = 0.0f;
    for (int i = tid; i < DD; i += 256) { float v = src[i]; s += v*v; }
    __shared__ float red[256];
    red[tid] = s; __syncthreads();
    for (int o = 128; o > 0; o >>= 1) { if (tid < o) red[tid] += red[tid+o]; __syncthreads(); }
    float inv = 1.0f / fmaxf(sqrtf(red[0]), 1e-12f);
    for (int i = tid; i < DD; i += 256) dst[i] = src[i] * inv;
}

// ---------------------------------------------------------------------------
// sw = softmax(sa_weights, axis=-1) * K
// ---------------------------------------------------------------------------
__global__ void sw_kernel(const float* __restrict__ sa) {
    int c = blockIdx.x * blockDim.x + threadIdx.x;
    if (c >= NCLS) return;
    float w[KP];
    float m = -1e30f;
    for (int k = 0; k < KP; k++) { w[k] = sa[c*KP+k]; m = fmaxf(m, w[k]); }
    float s = 0.0f;
    for (int k = 0; k < KP; k++) { w[k] = expf(w[k]-m); s += w[k]; }
    for (int k = 0; k < KP; k++) g_sw[c*KP+k] = w[k] / s * 5.0f;
}

// ---------------------------------------------------------------------------
// fp32 GEMM: logits[n, j] = dot(g_pt[n,:], g_pn[j,:])  n<12544, j<1005, d=768
// 128x64 block tile, 16 k-tile, 8x4 micro-tile per thread (256 threads)
// ---------------------------------------------------------------------------
#define TBM 128
#define TBN 64
#define TBK 16
__global__ __launch_bounds__(256) void gemm_kernel(float* __restrict__ out) {
    __shared__ float As[TBK][TBM+4];
    __shared__ float Bs[TBK][TBN+4];
    const int bm = blockIdx.x * TBM;
    const int bn = blockIdx.y * TBN;
    const int tid = threadIdx.x;
    const int tx = tid & 15;        // 0..15 -> N micro
    const int ty = tid >> 4;        // 0..15 -> M micro

    float acc[8][4];
    #pragma unroll
    for (int i = 0; i < 8; i++)
        #pragma unroll
        for (int j = 0; j < 4; j++) acc[i][j] = 0.0f;

    for (int kt = 0; kt < DD; kt += TBK) {
        // load A tile: 128 rows x 16 k  = 512 float4, 2 per thread
        #pragma unroll
        for (int l = 0; l < 2; l++) {
            int f  = tid + l*256;
            int m  = f >> 2;
            int kq = f & 3;
            const float4 v = *reinterpret_cast<const float4*>(g_pt + (size_t)(bm+m)*DD + kt + kq*4);
            As[kq*4+0][m] = v.x; As[kq*4+1][m] = v.y; As[kq*4+2][m] = v.z; As[kq*4+3][m] = v.w;
        }
        // load B tile: 64 rows x 16 k = 256 float4, 1 per thread
        {
            int f  = tid;
            int j  = f >> 2;
            int kq = f & 3;
            int row = bn + j;
            float4 v = make_float4(0.f,0.f,0.f,0.f);
            if (row < JJ)
                v = *reinterpret_cast<const float4*>(g_pn + (size_t)row*DD + kt + kq*4);
            Bs[kq*4+0][j] = v.x; Bs[kq*4+1][j] = v.y; Bs[kq*4+2][j] = v.z; Bs[kq*4+3][j] = v.w;
        }
        __syncthreads();
        #pragma unroll
        for (int k = 0; k < TBK; k++) {
            float a[8], b[4];
            float4 a0 = *reinterpret_cast<const float4*>(&As[k][ty*8]);
            float4 a1 = *reinterpret_cast<const float4*>(&As[k][ty*8+4]);
            a[0]=a0.x; a[1]=a0.y; a[2]=a0.z; a[3]=a0.w;
            a[4]=a1.x; a[5]=a1.y; a[6]=a1.z; a[7]=a1.w;
            float4 b0 = *reinterpret_cast<const float4*>(&Bs[k][tx*4]);
            b[0]=b0.x; b[1]=b0.y; b[2]=b0.z; b[3]=b0.w;
            #pragma unroll
            for (int i = 0; i < 8; i++)
                #pragma unroll
                for (int j = 0; j < 4; j++) acc[i][j] = fmaf(a[i], b[j], acc[i][j]);
        }
        __syncthreads();
    }
    // epilogue
    #pragma unroll
    for (int i = 0; i < 8; i++) {
        int row = bm + ty*8 + i;
        #pragma unroll
        for (int j = 0; j < 4; j++) {
            int col = bn + tx*4 + j;
            if (col < JJ) out[(size_t)row*JJ + col] = acc[i][j];
        }
    }
}

// ---------------------------------------------------------------------------
// image_logits[b, j] = max_p logits[b, p, j]
// ---------------------------------------------------------------------------
__global__ void imgmax_kernel(const float* __restrict__ logits, float* __restrict__ img) {
    int t = blockIdx.x * blockDim.x + threadIdx.x;
    if (t >= BB*JJ) return;
    int b = t / JJ, j = t % JJ;
    const float* p = logits + (size_t)b*PP*JJ + j;
    float m = -1e30f;
    for (int i = 0; i < PP; i++) m = fmaxf(m, p[(size_t)i*JJ]);
    img[(size_t)b*JJ + j] = m;
}

// ---------------------------------------------------------------------------
// class_logits[b, c] = sum_k img[b, c, k]*sw[c, k] / TEMP
// ---------------------------------------------------------------------------
__global__ void cls_kernel(const float* __restrict__ img, float* __restrict__ cls) {
    int t = blockIdx.x * blockDim.x + threadIdx.x;
    if (t >= BB*NCLS) return;
    int b = t / NCLS, c = t % NCLS;
    float s = 0.0f;
    #pragma unroll
    for (int k = 0; k < KP; k++) s += img[(size_t)b*JJ + c*KP + k] * g_sw[c*KP+k];
    cls[t] = s / 0.2f;
}

// ---------------------------------------------------------------------------
// Per-class: deterministic compaction + Sinkhorn + assignment + P_new
// ---------------------------------------------------------------------------
#define MAXN 1024
__global__ __launch_bounds__(256) void sinkhorn_kernel(
        const float* __restrict__ logits, const int* __restrict__ labels,
        const float* __restrict__ proto,
        float* __restrict__ assign, float* __restrict__ pnew) {
    const int c = blockIdx.x;
    const int tid = threadIdx.x;
    const int lane = tid & 31, w = tid >> 5;

    __shared__ int   s_idx[MAXN];
    __shared__ float Q[KP][MAXN];
    __shared__ float red[256];
    __shared__ int   warp_cnt[8], warp_off[8];
    __shared__ int   s_n;

    if (tid == 0) s_n = 0;
    __syncthreads();

    // ordered (deterministic) compaction of patch indices with label == c
    for (int base = 0; base < NN; base += 256) {
        int n = base + tid;
        bool p = (labels[n] == c);
        unsigned bal = __ballot_sync(0xffffffffu, p);
        if (lane == 0) warp_cnt[w] = __popc(bal);
        __syncthreads();
        if (tid == 0) {
            int s = s_n;
            #pragma unroll
            for (int i = 0; i < 8; i++) { warp_off[i] = s; s += warp_cnt[i]; }
            s_n = s;
        }
        __syncthreads();
        if (p) {
            int pos = warp_off[w] + __popc(bal & ((1u << lane) - 1u));
            if (pos < MAXN) s_idx[pos] = n;
        }
        __syncthreads();
    }
    const int Nc = min(s_n, MAXN);

    if (Nc == 0) {
        // absent class: P_new = prototypes, no patches to assign
        for (int x = tid; x < KP*DD; x += 256)
            pnew[(size_t)c*KP*DD + x] = proto[(size_t)c*KP*DD + x];
        return;
    }

    // Q = exp(L / 0.05)
    for (int i = tid; i < Nc; i += 256) {
        const float* lp = logits + (size_t)s_idx[i]*JJ + c*KP;
        #pragma unroll
        for (int k = 0; k < KP; k++) Q[k][i] = expf(lp[k] * 20.0f);
    }
    __syncthreads();

    // global normalization
    float s = 0.0f;
    for (int k = 0; k < KP; k++)
        for (int i = tid; i < Nc; i += 256) s += Q[k][i];
    red[tid] = s; __syncthreads();
    for (int o = 128; o > 0; o >>= 1) { if (tid < o) red[tid] += red[tid+o]; __syncthreads(); }
    float tot = red[0];
    __syncthreads();
    float dTot = (tot > 0.0f) ? tot : 1.0f;
    for (int k = 0; k < KP; k++)
        for (int i = tid; i < Nc; i += 256) Q[k][i] /= dTot;
    __syncthreads();

    const float fNc = (float)Nc;
    for (int it = 0; it < 3; it++) {
        // row (prototype) normalization, then / K
        for (int k = 0; k < KP; k++) {
            float rs = 0.0f;
            for (int i = tid; i < Nc; i += 256) rs += Q[k][i];
            red[tid] = rs; __syncthreads();
            for (int o = 128; o > 0; o >>= 1) { if (tid < o) red[tid] += red[tid+o]; __syncthreads(); }
            float r = red[0];
            __syncthreads();
            float dr = (r > 0.0f) ? r : 1.0f;
            for (int i = tid; i < Nc; i += 256) Q[k][i] = Q[k][i] / dr / 5.0f;
            __syncthreads();
        }
        // column (patch) normalization, then / Nc
        for (int i = tid; i < Nc; i += 256) {
            float cs = Q[0][i]+Q[1][i]+Q[2][i]+Q[3][i]+Q[4][i];
            float dc = (cs > 0.0f) ? cs : 1.0f;
            #pragma unroll
            for (int k = 0; k < KP; k++) Q[k][i] = Q[k][i] / dc / fNc;
        }
        __syncthreads();
    }
    // undo final /Nc
    for (int k = 0; k < KP; k++)
        for (int i = tid; i < Nc; i += 256) Q[k][i] *= fNc;
    __syncthreads();

    // part assignment: argmax_k (first max), + c*K
    for (int i = tid; i < Nc; i += 256) {
        float best = Q[0][i]; int ba = 0;
        #pragma unroll
        for (int k = 1; k < KP; k++) if (Q[k][i] > best) { best = Q[k][i]; ba = k; }
        assign[s_idx[i]] = (float)(c*KP + ba);
    }

    // P_new[c,k,:] = gamma*proto + (1-gamma) * sum_i Q[k][i] * rpt[idx_i,:]
    const int d0 = tid * 3;   // 256*3 = 768
    float acc[KP][3];
    #pragma unroll
    for (int k = 0; k < KP; k++) { acc[k][0]=0.f; acc[k][1]=0.f; acc[k][2]=0.f; }
    for (int i = 0; i < Nc; i++) {
        const float* xp = g_rpt + (size_t)s_idx[i]*DD + d0;
        float x0 = xp[0], x1 = xp[1], x2 = xp[2];
        #pragma unroll
        for (int k = 0; k < KP; k++) {
            float q = Q[k][i];
            acc[k][0] = fmaf(q, x0, acc[k][0]);
            acc[k][1] = fmaf(q, x1, acc[k][1]);
            acc[k][2] = fmaf(q, x2, acc[k][2]);
        }
    }
    const float g = 0.999f, og = 1.0f - 0.999f;
    #pragma unroll
    for (int k = 0; k < KP; k++) {
        size_t basep = ((size_t)c*KP + k)*DD + d0;
        #pragma unroll
        for (int j = 0; j < 3; j++)
            pnew[basep + j] = g * proto[basep + j] + og * acc[k][j];
    }
}

// ---------------------------------------------------------------------------
extern "C" void kernel_launch(void* const* d_in, const int* in_sizes, int n_in,
                              void* d_out, int out_size) {
    const float* pt    = (const float*)d_in[0];
    const float* rpt   = (const float*)d_in[1];
    const float* proto = (const float*)d_in[2];
    const float* sa    = (const float*)d_in[3];
    const int*   lbl   = (const int*)  d_in[4];
    float* out = (float*)d_out;

    norm_kernel<<<2*NN + JJ, 256>>>(pt, rpt, proto);
    sw_kernel<<<1, 256>>>(sa);
    {
        dim3 grid(NN/TBM, (JJ + TBN - 1)/TBN);
        gemm_kernel<<<grid, 256>>>(out + OFF_LOGITS);
    }
    imgmax_kernel<<<(BB*JJ + 255)/256, 256>>>(out + OFF_LOGITS, out + OFF_IMG);
    cls_kernel<<<(BB*NCLS + 255)/256, 256>>>(out + OFF_IMG, out + OFF_CLS);
    sinkhorn_kernel<<<CC, 256>>>(out + OFF_LOGITS, lbl, proto,
                                 out + OFF_ASGN, out + OFF_PNEW);
}

// round 4
// speedup vs baseline: 1.7650x; 1.7650x over previous
#include <cuda_runtime.h>
#include <cuda_bf16.h>
#include <cstdint>
#include <math.h>

// Problem constants
#define BB 64
#define PP 196
#define DD 768
#define CC 201
#define KP 5
#define NCLS 200
#define NN (BB*PP)        // 12544
#define JJ (CC*KP)        // 1005
#define JPAD 1024

// Output layout (float32, concatenated in reference return order)
#define OFF_LOGITS 0
#define SZ_LOGITS  (NN*JJ)
#define OFF_IMG    (OFF_LOGITS + SZ_LOGITS)
#define SZ_IMG     (BB*JJ)
#define OFF_CLS    (OFF_IMG + SZ_IMG)
#define SZ_CLS     (BB*NCLS)
#define OFF_ASGN   (OFF_CLS + SZ_CLS)
#define SZ_ASGN    (NN)
#define OFF_PNEW   (OFF_ASGN + SZ_ASGN)
#define SZ_PNEW    (CC*KP*DD)

// Device scratch
__device__ __nv_bfloat16 g_pth[NN*DD];     // normalized patch tokens, hi part
__device__ __nv_bfloat16 g_ptl[NN*DD];     // lo part
__device__ float         g_rpt[NN*DD];     // normalized raw patch tokens (fp32)
__device__ __nv_bfloat16 g_pnh[JPAD*DD];   // normalized prototypes hi (padded rows zero)
__device__ __nv_bfloat16 g_pnl[JPAD*DD];   // lo
__device__ float         g_sw[NCLS*KP];    // softmax(sa_weights)*K

// ---------------------------------------------------------------------------
// warp MMA helpers (sm_80+ PTX, works on sm_103)
// ---------------------------------------------------------------------------
__device__ __forceinline__ void ldsm_x4(uint32_t* r, uint32_t addr) {
    asm volatile("ldmatrix.sync.aligned.m8n8.x4.shared.b16 {%0,%1,%2,%3}, [%4];"
                 : "=r"(r[0]), "=r"(r[1]), "=r"(r[2]), "=r"(r[3]) : "r"(addr));
}
__device__ __forceinline__ void mma_bf16(float* d, const uint32_t* a, const uint32_t* b) {
    asm volatile(
        "mma.sync.aligned.m16n8k16.row.col.f32.bf16.bf16.f32 "
        "{%0,%1,%2,%3}, {%4,%5,%6,%7}, {%8,%9}, {%0,%1,%2,%3};"
        : "+f"(d[0]), "+f"(d[1]), "+f"(d[2]), "+f"(d[3])
        : "r"(a[0]), "r"(a[1]), "r"(a[2]), "r"(a[3]), "r"(b[0]), "r"(b[1]));
}

// ---------------------------------------------------------------------------
// Row L2 normalization + bf16 hi/lo split
// ---------------------------------------------------------------------------
__global__ void norm_kernel(const float* __restrict__ pt,
                            const float* __restrict__ rpt,
                            const float* __restrict__ proto) {
    int r = blockIdx.x;
    int tid = threadIdx.x;
    __shared__ float red[256];

    if (r < NN) {
        const float* src = pt + (size_t)r*DD;
        float s = 0.0f;
        for (int i = tid; i < DD; i += 256) { float v = src[i]; s += v*v; }
        red[tid] = s; __syncthreads();
        for (int o = 128; o > 0; o >>= 1) { if (tid < o) red[tid] += red[tid+o]; __syncthreads(); }
        float inv = 1.0f / fmaxf(sqrtf(red[0]), 1e-12f);
        for (int i = tid; i < DD; i += 256) {
            float x = src[i] * inv;
            __nv_bfloat16 hi = __float2bfloat16(x);
            float lo = x - __bfloat162float(hi);
            g_pth[(size_t)r*DD + i] = hi;
            g_ptl[(size_t)r*DD + i] = __float2bfloat16(lo);
        }
    } else if (r < 2*NN) {
        int rr = r - NN;
        const float* src = rpt + (size_t)rr*DD;
        float s = 0.0f;
        for (int i = tid; i < DD; i += 256) { float v = src[i]; s += v*v; }
        red[tid] = s; __syncthreads();
        for (int o = 128; o > 0; o >>= 1) { if (tid < o) red[tid] += red[tid+o]; __syncthreads(); }
        float inv = 1.0f / fmaxf(sqrtf(red[0]), 1e-12f);
        for (int i = tid; i < DD; i += 256) g_rpt[(size_t)rr*DD + i] = src[i] * inv;
    } else {
        int j = r - 2*NN;   // 0..JPAD-1
        if (j >= JJ) {
            __nv_bfloat16 z = __float2bfloat16(0.0f);
            for (int i = tid; i < DD; i += 256) {
                g_pnh[(size_t)j*DD + i] = z;
                g_pnl[(size_t)j*DD + i] = z;
            }
            return;
        }
        const float* src = proto + (size_t)j*DD;
        float s = 0.0f;
        for (int i = tid; i < DD; i += 256) { float v = src[i]; s += v*v; }
        red[tid] = s; __syncthreads();
        for (int o = 128; o > 0; o >>= 1) { if (tid < o) red[tid] += red[tid+o]; __syncthreads(); }
        float inv = 1.0f / fmaxf(sqrtf(red[0]), 1e-12f);
        for (int i = tid; i < DD; i += 256) {
            float x = src[i] * inv;
            __nv_bfloat16 hi = __float2bfloat16(x);
            float lo = x - __bfloat162float(hi);
            g_pnh[(size_t)j*DD + i] = hi;
            g_pnl[(size_t)j*DD + i] = __float2bfloat16(lo);
        }
    }
}

// ---------------------------------------------------------------------------
// sw = softmax(sa_weights, axis=-1) * K
// ---------------------------------------------------------------------------
__global__ void sw_kernel(const float* __restrict__ sa) {
    int c = blockIdx.x * blockDim.x + threadIdx.x;
    if (c >= NCLS) return;
    float w[KP];
    float m = -1e30f;
    for (int k = 0; k < KP; k++) { w[k] = sa[c*KP+k]; m = fmaxf(m, w[k]); }
    float s = 0.0f;
    for (int k = 0; k < KP; k++) { w[k] = expf(w[k]-m); s += w[k]; }
    for (int k = 0; k < KP; k++) g_sw[c*KP+k] = w[k] / s * 5.0f;
}

// ---------------------------------------------------------------------------
// split-bf16 mma.sync GEMM:  logits = pt_norm @ proto_norm^T
// CTA 128x128, BK=32, 8 warps (4M x 2N), warp tile 32x64
// D = Ah*Bh + Ah*Bl + Al*Bh  (fp32 accumulate)
// ---------------------------------------------------------------------------
#define SAS 40   // smem row stride in bf16 elems (32 + 8 pad) -> conflict-free ldmatrix

__global__ __launch_bounds__(256, 2) void gemm_mma_kernel(float* __restrict__ out) {
    __shared__ __align__(16) __nv_bfloat16 sAh[128*SAS];
    __shared__ __align__(16) __nv_bfloat16 sAl[128*SAS];
    __shared__ __align__(16) __nv_bfloat16 sBh[128*SAS];
    __shared__ __align__(16) __nv_bfloat16 sBl[128*SAS];

    const int tid  = threadIdx.x;
    const int lane = tid & 31;
    const int wid  = tid >> 5;
    const int wm   = wid & 3;      // 0..3 -> M block of 32
    const int wn   = wid >> 2;     // 0..1 -> N block of 64
    const int bm   = blockIdx.x * 128;
    const int bn   = blockIdx.y * 128;

    const uint32_t aAh = (uint32_t)__cvta_generic_to_shared(sAh);
    const uint32_t aAl = (uint32_t)__cvta_generic_to_shared(sAl);
    const uint32_t aBh = (uint32_t)__cvta_generic_to_shared(sBh);
    const uint32_t aBl = (uint32_t)__cvta_generic_to_shared(sBl);

    // ldmatrix per-thread address components
    const int arow = (lane & 7) + ((lane >> 3) & 1) * 8;
    const int acol = (lane >> 4) * 8;
    const int brow = (lane & 7) + ((lane >> 4) & 1) * 8;
    const int bcol = ((lane >> 3) & 1) * 8;

    float acc[2][8][4];
    #pragma unroll
    for (int i = 0; i < 2; i++)
        #pragma unroll
        for (int j = 0; j < 8; j++)
            #pragma unroll
            for (int q = 0; q < 4; q++) acc[i][j][q] = 0.0f;

    // global load indices: 2 chunks of 16B per array per thread
    const int gr0 = tid >> 2;          // row (0..63)
    const int gq0 = tid & 3;           // 16B col chunk
    for (int kt = 0; kt < DD; kt += 32) {
        #pragma unroll
        for (int l = 0; l < 2; l++) {
            int row = gr0 + l*64;
            size_t gi = (size_t)(bm + row)*DD + kt + gq0*8;
            int so = row*SAS + gq0*8;
            *(float4*)(sAh + so) = *(const float4*)(g_pth + gi);
            *(float4*)(sAl + so) = *(const float4*)(g_ptl + gi);
            size_t gj = (size_t)(bn + row)*DD + kt + gq0*8;
            *(float4*)(sBh + so) = *(const float4*)(g_pnh + gj);
            *(float4*)(sBl + so) = *(const float4*)(g_pnl + gj);
        }
        __syncthreads();

        #pragma unroll
        for (int ks = 0; ks < 32; ks += 16) {
            uint32_t ah[2][4], al[2][4];
            #pragma unroll
            for (int mi = 0; mi < 2; mi++) {
                uint32_t off = (uint32_t)((wm*32 + mi*16 + arow)*SAS + ks + acol) * 2;
                ldsm_x4(ah[mi], aAh + off);
                ldsm_x4(al[mi], aAl + off);
            }
            #pragma unroll
            for (int nb = 0; nb < 4; nb++) {
                uint32_t bh[4], bl[4];
                uint32_t off = (uint32_t)((wn*64 + nb*16 + brow)*SAS + ks + bcol) * 2;
                ldsm_x4(bh, aBh + off);
                ldsm_x4(bl, aBl + off);
                #pragma unroll
                for (int mi = 0; mi < 2; mi++) {
                    mma_bf16(acc[mi][nb*2+0], ah[mi], bh+0);
                    mma_bf16(acc[mi][nb*2+0], ah[mi], bl+0);
                    mma_bf16(acc[mi][nb*2+0], al[mi], bh+0);
                    mma_bf16(acc[mi][nb*2+1], ah[mi], bh+2);
                    mma_bf16(acc[mi][nb*2+1], ah[mi], bl+2);
                    mma_bf16(acc[mi][nb*2+1], al[mi], bh+2);
                }
            }
        }
        __syncthreads();
    }

    // epilogue: scalar fp32 stores (JJ=1005 is odd -> vector stores misalign)
    #pragma unroll
    for (int mi = 0; mi < 2; mi++) {
        #pragma unroll
        for (int nf = 0; nf < 8; nf++) {
            int col = bn + wn*64 + nf*8 + (lane & 3)*2;
            #pragma unroll
            for (int h = 0; h < 2; h++) {   // d0,d1 (row) / d2,d3 (row+8)
                int row = bm + wm*32 + mi*16 + (lane >> 2) + h*8;
                size_t base = (size_t)row*JJ + col;
                if (col < JJ)     out[base]     = acc[mi][nf][h*2+0];
                if (col + 1 < JJ) out[base + 1] = acc[mi][nf][h*2+1];
            }
        }
    }
}

// ---------------------------------------------------------------------------
// image_logits[b, j] = max_p logits[b, p, j]
// ---------------------------------------------------------------------------
__global__ void imgmax_kernel(const float* __restrict__ logits, float* __restrict__ img) {
    int t = blockIdx.x * blockDim.x + threadIdx.x;
    if (t >= BB*JJ) return;
    int b = t / JJ, j = t % JJ;
    const float* p = logits + (size_t)b*PP*JJ + j;
    float m = -1e30f;
    for (int i = 0; i < PP; i++) m = fmaxf(m, p[(size_t)i*JJ]);
    img[(size_t)b*JJ + j] = m;
}

// ---------------------------------------------------------------------------
// class_logits[b, c] = sum_k img[b, c, k]*sw[c, k] / TEMP
// ---------------------------------------------------------------------------
__global__ void cls_kernel(const float* __restrict__ img, float* __restrict__ cls) {
    int t = blockIdx.x * blockDim.x + threadIdx.x;
    if (t >= BB*NCLS) return;
    int b = t / NCLS, c = t % NCLS;
    float s = 0.0f;
    #pragma unroll
    for (int k = 0; k < KP; k++) s += img[(size_t)b*JJ + c*KP + k] * g_sw[c*KP+k];
    cls[t] = s / 0.2f;
}

// ---------------------------------------------------------------------------
// Per-class: deterministic compaction + Sinkhorn + assignment + P_new
// ---------------------------------------------------------------------------
#define MAXN 1024
__global__ __launch_bounds__(256) void sinkhorn_kernel(
        const float* __restrict__ logits, const int* __restrict__ labels,
        const float* __restrict__ proto,
        float* __restrict__ assign, float* __restrict__ pnew) {
    const int c = blockIdx.x;
    const int tid = threadIdx.x;
    const int lane = tid & 31, w = tid >> 5;

    __shared__ int   s_idx[MAXN];
    __shared__ float Q[KP][MAXN];
    __shared__ float red[256];
    __shared__ int   warp_cnt[8], warp_off[8];
    __shared__ int   s_n;

    if (tid == 0) s_n = 0;
    __syncthreads();

    for (int base = 0; base < NN; base += 256) {
        int n = base + tid;
        bool p = (labels[n] == c);
        unsigned bal = __ballot_sync(0xffffffffu, p);
        if (lane == 0) warp_cnt[w] = __popc(bal);
        __syncthreads();
        if (tid == 0) {
            int s = s_n;
            #pragma unroll
            for (int i = 0; i < 8; i++) { warp_off[i] = s; s += warp_cnt[i]; }
            s_n = s;
        }
        __syncthreads();
        if (p) {
            int pos = warp_off[w] + __popc(bal & ((1u << lane) - 1u));
            if (pos < MAXN) s_idx[pos] = n;
        }
        __syncthreads();
    }
    const int Nc = min(s_n, MAXN);

    if (Nc == 0) {
        for (int x = tid; x < KP*DD; x += 256)
            pnew[(size_t)c*KP*DD + x] = proto[(size_t)c*KP*DD + x];
        return;
    }

    for (int i = tid; i < Nc; i += 256) {
        const float* lp = logits + (size_t)s_idx[i]*JJ + c*KP;
        #pragma unroll
        for (int k = 0; k < KP; k++) Q[k][i] = expf(lp[k] * 20.0f);
    }
    __syncthreads();

    float s = 0.0f;
    for (int k = 0; k < KP; k++)
        for (int i = tid; i < Nc; i += 256) s += Q[k][i];
    red[tid] = s; __syncthreads();
    for (int o = 128; o > 0; o >>= 1) { if (tid < o) red[tid] += red[tid+o]; __syncthreads(); }
    float tot = red[0];
    __syncthreads();
    float dTot = (tot > 0.0f) ? tot : 1.0f;
    for (int k = 0; k < KP; k++)
        for (int i = tid; i < Nc; i += 256) Q[k][i] /= dTot;
    __syncthreads();

    const float fNc = (float)Nc;
    for (int it = 0; it < 3; it++) {
        for (int k = 0; k < KP; k++) {
            float rs = 0.0f;
            for (int i = tid; i < Nc; i += 256) rs += Q[k][i];
            red[tid] = rs; __syncthreads();
            for (int o = 128; o > 0; o >>= 1) { if (tid < o) red[tid] += red[tid+o]; __syncthreads(); }
            float r = red[0];
            __syncthreads();
            float dr = (r > 0.0f) ? r : 1.0f;
            for (int i = tid; i < Nc; i += 256) Q[k][i] = Q[k][i] / dr / 5.0f;
            __syncthreads();
        }
        for (int i = tid; i < Nc; i += 256) {
            float cs = Q[0][i]+Q[1][i]+Q[2][i]+Q[3][i]+Q[4][i];
            float dc = (cs > 0.0f) ? cs : 1.0f;
            #pragma unroll
            for (int k = 0; k < KP; k++) Q[k][i] = Q[k][i] / dc / fNc;
        }
        __syncthreads();
    }
    for (int k = 0; k < KP; k++)
        for (int i = tid; i < Nc; i += 256) Q[k][i] *= fNc;
    __syncthreads();

    for (int i = tid; i < Nc; i += 256) {
        float best = Q[0][i]; int ba = 0;
        #pragma unroll
        for (int k = 1; k < KP; k++) if (Q[k][i] > best) { best = Q[k][i]; ba = k; }
        assign[s_idx[i]] = (float)(c*KP + ba);
    }

    const int d0 = tid * 3;
    float acc[KP][3];
    #pragma unroll
    for (int k = 0; k < KP; k++) { acc[k][0]=0.f; acc[k][1]=0.f; acc[k][2]=0.f; }
    for (int i = 0; i < Nc; i++) {
        const float* xp = g_rpt + (size_t)s_idx[i]*DD + d0;
        float x0 = xp[0], x1 = xp[1], x2 = xp[2];
        #pragma unroll
        for (int k = 0; k < KP; k++) {
            float q = Q[k][i];
            acc[k][0] = fmaf(q, x0, acc[k][0]);
            acc[k][1] = fmaf(q, x1, acc[k][1]);
            acc[k][2] = fmaf(q, x2, acc[k][2]);
        }
    }
    const float g = 0.999f, og = 1.0f - 0.999f;
    #pragma unroll
    for (int k = 0; k < KP; k++) {
        size_t basep = ((size_t)c*KP + k)*DD + d0;
        #pragma unroll
        for (int j = 0; j < 3; j++)
            pnew[basep + j] = g * proto[basep + j] + og * acc[k][j];
    }
}

// ---------------------------------------------------------------------------
extern "C" void kernel_launch(void* const* d_in, const int* in_sizes, int n_in,
                              void* d_out, int out_size) {
    const float* pt    = (const float*)d_in[0];
    const float* rpt   = (const float*)d_in[1];
    const float* proto = (const float*)d_in[2];
    const float* sa    = (const float*)d_in[3];
    const int*   lbl   = (const int*)  d_in[4];
    float* out = (float*)d_out;

    norm_kernel<<<2*NN + JPAD, 256>>>(pt, rpt, proto);
    sw_kernel<<<1, 256>>>(sa);
    {
        dim3 grid(NN/128, JPAD/128);   // 98 x 8
        gemm_mma_kernel<<<grid, 256>>>(out + OFF_LOGITS);
    }
    imgmax_kernel<<<(BB*JJ + 255)/256, 256>>>(out + OFF_LOGITS, out + OFF_IMG);
    cls_kernel<<<(BB*NCLS + 255)/256, 256>>>(out + OFF_IMG, out + OFF_CLS);
    sinkhorn_kernel<<<CC, 256>>>(out + OFF_LOGITS, lbl, proto,
                                 out + OFF_ASGN, out + OFF_PNEW);
}

// round 5
// speedup vs baseline: 1.8973x; 1.0750x over previous
#include <cuda_runtime.h>
#include <cuda_bf16.h>
#include <cstdint>
#include <math.h>

// Problem constants
#define BB 64
#define PP 196
#define DD 768
#define CC 201
#define KP 5
#define NCLS 200
#define NN (BB*PP)        // 12544
#define JJ (CC*KP)        // 1005
#define JPAD 1024

// Output layout (float32, concatenated in reference return order)
#define OFF_LOGITS 0
#define SZ_LOGITS  (NN*JJ)
#define OFF_IMG    (OFF_LOGITS + SZ_LOGITS)
#define SZ_IMG     (BB*JJ)
#define OFF_CLS    (OFF_IMG + SZ_IMG)
#define SZ_CLS     (BB*NCLS)
#define OFF_ASGN   (OFF_CLS + SZ_CLS)
#define SZ_ASGN    (NN)
#define OFF_PNEW   (OFF_ASGN + SZ_ASGN)
#define SZ_PNEW    (CC*KP*DD)

// Device scratch
__device__ __align__(16) __nv_bfloat16 g_pth[NN*DD];
__device__ __align__(16) __nv_bfloat16 g_ptl[NN*DD];
__device__ __align__(16) float         g_rpt[NN*DD];
__device__ __align__(16) __nv_bfloat16 g_pnh[JPAD*DD];
__device__ __align__(16) __nv_bfloat16 g_pnl[JPAD*DD];
__device__ float g_sw[NCLS*KP];

// ---------------------------------------------------------------------------
// PTX helpers
// ---------------------------------------------------------------------------
__device__ __forceinline__ void ldsm_x4(uint32_t* r, uint32_t addr) {
    asm volatile("ldmatrix.sync.aligned.m8n8.x4.shared.b16 {%0,%1,%2,%3}, [%4];"
                 : "=r"(r[0]), "=r"(r[1]), "=r"(r[2]), "=r"(r[3]) : "r"(addr));
}
__device__ __forceinline__ void mma_bf16(float* d, const uint32_t* a, const uint32_t* b) {
    asm volatile(
        "mma.sync.aligned.m16n8k16.row.col.f32.bf16.bf16.f32 "
        "{%0,%1,%2,%3}, {%4,%5,%6,%7}, {%8,%9}, {%0,%1,%2,%3};"
        : "+f"(d[0]), "+f"(d[1]), "+f"(d[2]), "+f"(d[3])
        : "r"(a[0]), "r"(a[1]), "r"(a[2]), "r"(a[3]), "r"(b[0]), "r"(b[1]));
}
__device__ __forceinline__ void cpa16(uint32_t smem, const void* g) {
    asm volatile("cp.async.ca.shared.global [%0], [%1], 16;" :: "r"(smem), "l"(g));
}
__device__ __forceinline__ void cpa_commit() {
    asm volatile("cp.async.commit_group;" ::: "memory");
}
template <int N>
__device__ __forceinline__ void cpa_wait() {
    asm volatile("cp.async.wait_group %0;" :: "n"(N) : "memory");
}

// ---------------------------------------------------------------------------
// Row L2 normalization + bf16 hi/lo split (warp per row)
// rows [0,NN): pt ; [NN,2NN): rpt ; [2NN,2NN+JPAD): protos (pad rows zero)
// ---------------------------------------------------------------------------
__global__ __launch_bounds__(256) void norm_kernel(const float* __restrict__ pt,
                            const float* __restrict__ rpt,
                            const float* __restrict__ proto) {
    const int r = blockIdx.x * 8 + (threadIdx.x >> 5);
    const int lane = threadIdx.x & 31;
    if (r >= 2*NN + JPAD) return;

    if (r < NN) {
        const float* src = pt + (size_t)r*DD;
        float s = 0.0f;
        for (int i = lane; i < DD; i += 32) { float v = src[i]; s += v*v; }
        #pragma unroll
        for (int o = 16; o > 0; o >>= 1) s += __shfl_xor_sync(0xffffffffu, s, o);
        float inv = 1.0f / fmaxf(sqrtf(s), 1e-12f);
        for (int i = lane; i < DD; i += 32) {
            float x = src[i] * inv;
            __nv_bfloat16 hi = __float2bfloat16(x);
            g_pth[(size_t)r*DD + i] = hi;
            g_ptl[(size_t)r*DD + i] = __float2bfloat16(x - __bfloat162float(hi));
        }
    } else if (r < 2*NN) {
        int rr = r - NN;
        const float* src = rpt + (size_t)rr*DD;
        float s = 0.0f;
        for (int i = lane; i < DD; i += 32) { float v = src[i]; s += v*v; }
        #pragma unroll
        for (int o = 16; o > 0; o >>= 1) s += __shfl_xor_sync(0xffffffffu, s, o);
        float inv = 1.0f / fmaxf(sqrtf(s), 1e-12f);
        for (int i = lane; i < DD; i += 32) g_rpt[(size_t)rr*DD + i] = src[i] * inv;
    } else {
        int j = r - 2*NN;
        if (j >= JJ) {
            __nv_bfloat16 z = __float2bfloat16(0.0f);
            for (int i = lane; i < DD; i += 32) {
                g_pnh[(size_t)j*DD + i] = z;
                g_pnl[(size_t)j*DD + i] = z;
            }
            return;
        }
        const float* src = proto + (size_t)j*DD;
        float s = 0.0f;
        for (int i = lane; i < DD; i += 32) { float v = src[i]; s += v*v; }
        #pragma unroll
        for (int o = 16; o > 0; o >>= 1) s += __shfl_xor_sync(0xffffffffu, s, o);
        float inv = 1.0f / fmaxf(sqrtf(s), 1e-12f);
        for (int i = lane; i < DD; i += 32) {
            float x = src[i] * inv;
            __nv_bfloat16 hi = __float2bfloat16(x);
            g_pnh[(size_t)j*DD + i] = hi;
            g_pnl[(size_t)j*DD + i] = __float2bfloat16(x - __bfloat162float(hi));
        }
    }
}

// ---------------------------------------------------------------------------
// sw = softmax(sa_weights, axis=-1) * K
// ---------------------------------------------------------------------------
__global__ void sw_kernel(const float* __restrict__ sa) {
    int c = blockIdx.x * blockDim.x + threadIdx.x;
    if (c >= NCLS) return;
    float w[KP];
    float m = -1e30f;
    for (int k = 0; k < KP; k++) { w[k] = sa[c*KP+k]; m = fmaxf(m, w[k]); }
    float s = 0.0f;
    for (int k = 0; k < KP; k++) { w[k] = expf(w[k]-m); s += w[k]; }
    for (int k = 0; k < KP; k++) g_sw[c*KP+k] = w[k] / s * 5.0f;
}

// ---------------------------------------------------------------------------
// split-bf16 mma.sync GEMM with cp.async 2-stage pipeline
// CTA 128x128, BK=32, 8 warps (4M x 2N); D = Ah*Bh + Ah*Bl + Al*Bh
// ---------------------------------------------------------------------------
#define SAS 40                         // smem row stride (bf16 elems)
#define TILE_BYTES (128*SAS*2)         // 10240 per array per stage
#define NCHUNK (DD/32)                 // 24
// array order: Ah, Al, Bh, Bl ; addr(arr, stage) = (arr*2 + stage)*TILE_BYTES
#define SMEM_GEMM (8*TILE_BYTES)       // 81920

__global__ __launch_bounds__(256, 2) void gemm_mma_kernel(float* __restrict__ out) {
    extern __shared__ __align__(16) char smem[];
    const uint32_t sb = (uint32_t)__cvta_generic_to_shared(smem);

    const int tid  = threadIdx.x;
    const int lane = tid & 31;
    const int wid  = tid >> 5;
    const int wm   = wid & 3;
    const int wn   = wid >> 2;
    const int bm   = blockIdx.x * 128;
    const int bn   = blockIdx.y * 128;

    const int arow = (lane & 7) + ((lane >> 3) & 1) * 8;
    const int acol = (lane >> 4) * 8;
    const int brow = (lane & 7) + ((lane >> 4) & 1) * 8;
    const int bcol = ((lane >> 3) & 1) * 8;

    float acc[2][8][4];
    #pragma unroll
    for (int i = 0; i < 2; i++)
        #pragma unroll
        for (int j = 0; j < 8; j++)
            #pragma unroll
            for (int q = 0; q < 4; q++) acc[i][j][q] = 0.0f;

    const int gr0 = tid >> 2;          // row (0..63), +64 for second half
    const int gq0 = tid & 3;           // 16B chunk within 32-col tile

    // async load of one K-chunk into stage s
    auto load_chunk = [&](int kt, int s) {
        #pragma unroll
        for (int l = 0; l < 2; l++) {
            int row = gr0 + l*64;
            uint32_t so = (uint32_t)(row*SAS + gq0*8) * 2;
            size_t gi = (size_t)(bm + row)*DD + kt + gq0*8;
            size_t gj = (size_t)(bn + row)*DD + kt + gq0*8;
            cpa16(sb + (0*2 + s)*TILE_BYTES + so, g_pth + gi);
            cpa16(sb + (1*2 + s)*TILE_BYTES + so, g_ptl + gi);
            cpa16(sb + (2*2 + s)*TILE_BYTES + so, g_pnh + gj);
            cpa16(sb + (3*2 + s)*TILE_BYTES + so, g_pnl + gj);
        }
        cpa_commit();
    };

    load_chunk(0, 0);

    for (int i = 0; i < NCHUNK; i++) {
        const int s = i & 1;
        if (i + 1 < NCHUNK) {
            load_chunk((i+1)*32, (i+1) & 1);
            cpa_wait<1>();
        } else {
            cpa_wait<0>();
        }
        __syncthreads();

        const uint32_t aAh = sb + (0*2 + s)*TILE_BYTES;
        const uint32_t aAl = sb + (1*2 + s)*TILE_BYTES;
        const uint32_t aBh = sb + (2*2 + s)*TILE_BYTES;
        const uint32_t aBl = sb + (3*2 + s)*TILE_BYTES;

        #pragma unroll
        for (int ks = 0; ks < 32; ks += 16) {
            uint32_t ah[2][4], al[2][4];
            #pragma unroll
            for (int mi = 0; mi < 2; mi++) {
                uint32_t off = (uint32_t)((wm*32 + mi*16 + arow)*SAS + ks + acol) * 2;
                ldsm_x4(ah[mi], aAh + off);
                ldsm_x4(al[mi], aAl + off);
            }
            #pragma unroll
            for (int nb = 0; nb < 4; nb++) {
                uint32_t bh[4], bl[4];
                uint32_t off = (uint32_t)((wn*64 + nb*16 + brow)*SAS + ks + bcol) * 2;
                ldsm_x4(bh, aBh + off);
                ldsm_x4(bl, aBl + off);
                #pragma unroll
                for (int mi = 0; mi < 2; mi++) {
                    mma_bf16(acc[mi][nb*2+0], ah[mi], bh+0);
                    mma_bf16(acc[mi][nb*2+0], ah[mi], bl+0);
                    mma_bf16(acc[mi][nb*2+0], al[mi], bh+0);
                    mma_bf16(acc[mi][nb*2+1], ah[mi], bh+2);
                    mma_bf16(acc[mi][nb*2+1], ah[mi], bl+2);
                    mma_bf16(acc[mi][nb*2+1], al[mi], bh+2);
                }
            }
        }
        __syncthreads();
    }

    // epilogue: scalar fp32 stores (JJ odd -> no vector stores)
    #pragma unroll
    for (int mi = 0; mi < 2; mi++) {
        #pragma unroll
        for (int nf = 0; nf < 8; nf++) {
            int col = bn + wn*64 + nf*8 + (lane & 3)*2;
            #pragma unroll
            for (int h = 0; h < 2; h++) {
                int row = bm + wm*32 + mi*16 + (lane >> 2) + h*8;
                size_t base = (size_t)row*JJ + col;
                if (col < JJ)     out[base]     = acc[mi][nf][h*2+0];
                if (col + 1 < JJ) out[base + 1] = acc[mi][nf][h*2+1];
            }
        }
    }
}

// ---------------------------------------------------------------------------
// image_logits[b, j] = max_p logits[b, p, j]
// ---------------------------------------------------------------------------
__global__ void imgmax_kernel(const float* __restrict__ logits, float* __restrict__ img) {
    int t = blockIdx.x * blockDim.x + threadIdx.x;
    if (t >= BB*JJ) return;
    int b = t / JJ, j = t % JJ;
    const float* p = logits + (size_t)b*PP*JJ + j;
    float m = -1e30f;
    for (int i = 0; i < PP; i++) m = fmaxf(m, p[(size_t)i*JJ]);
    img[(size_t)b*JJ + j] = m;
}

// ---------------------------------------------------------------------------
// class_logits[b, c] = sum_k img[b, c, k]*sw[c, k] / TEMP
// ---------------------------------------------------------------------------
__global__ void cls_kernel(const float* __restrict__ img, float* __restrict__ cls) {
    int t = blockIdx.x * blockDim.x + threadIdx.x;
    if (t >= BB*NCLS) return;
    int b = t / NCLS, c = t % NCLS;
    float s = 0.0f;
    #pragma unroll
    for (int k = 0; k < KP; k++) s += img[(size_t)b*JJ + c*KP + k] * g_sw[c*KP+k];
    cls[t] = s / 0.2f;
}

// ---------------------------------------------------------------------------
// Per-class: deterministic compaction + Sinkhorn + assignment + P_new
// ---------------------------------------------------------------------------
#define MAXN 1024
__global__ __launch_bounds__(256) void sinkhorn_kernel(
        const float* __restrict__ logits, const int* __restrict__ labels,
        const float* __restrict__ proto,
        float* __restrict__ assign, float* __restrict__ pnew) {
    const int c = blockIdx.x;
    const int tid = threadIdx.x;
    const int lane = tid & 31, w = tid >> 5;

    __shared__ int   s_idx[MAXN];
    __shared__ float Q[KP][MAXN];
    __shared__ float red[256];
    __shared__ int   warp_cnt[8], warp_off[8];
    __shared__ int   s_n;

    if (tid == 0) s_n = 0;
    __syncthreads();

    for (int base = 0; base < NN; base += 256) {
        int n = base + tid;
        bool p = (labels[n] == c);
        unsigned bal = __ballot_sync(0xffffffffu, p);
        if (lane == 0) warp_cnt[w] = __popc(bal);
        __syncthreads();
        if (tid == 0) {
            int s = s_n;
            #pragma unroll
            for (int i = 0; i < 8; i++) { warp_off[i] = s; s += warp_cnt[i]; }
            s_n = s;
        }
        __syncthreads();
        if (p) {
            int pos = warp_off[w] + __popc(bal & ((1u << lane) - 1u));
            if (pos < MAXN) s_idx[pos] = n;
        }
        __syncthreads();
    }
    const int Nc = min(s_n, MAXN);

    if (Nc == 0) {
        for (int x = tid; x < KP*DD; x += 256)
            pnew[(size_t)c*KP*DD + x] = proto[(size_t)c*KP*DD + x];
        return;
    }

    for (int i = tid; i < Nc; i += 256) {
        const float* lp = logits + (size_t)s_idx[i]*JJ + c*KP;
        #pragma unroll
        for (int k = 0; k < KP; k++) Q[k][i] = expf(lp[k] * 20.0f);
    }
    __syncthreads();

    float s = 0.0f;
    for (int k = 0; k < KP; k++)
        for (int i = tid; i < Nc; i += 256) s += Q[k][i];
    red[tid] = s; __syncthreads();
    for (int o = 128; o > 0; o >>= 1) { if (tid < o) red[tid] += red[tid+o]; __syncthreads(); }
    float tot = red[0];
    __syncthreads();
    float dTot = (tot > 0.0f) ? tot : 1.0f;
    for (int k = 0; k < KP; k++)
        for (int i = tid; i < Nc; i += 256) Q[k][i] /= dTot;
    __syncthreads();

    const float fNc = (float)Nc;
    for (int it = 0; it < 3; it++) {
        for (int k = 0; k < KP; k++) {
            float rs = 0.0f;
            for (int i = tid; i < Nc; i += 256) rs += Q[k][i];
            red[tid] = rs; __syncthreads();
            for (int o = 128; o > 0; o >>= 1) { if (tid < o) red[tid] += red[tid+o]; __syncthreads(); }
            float r = red[0];
            __syncthreads();
            float dr = (r > 0.0f) ? r : 1.0f;
            for (int i = tid; i < Nc; i += 256) Q[k][i] = Q[k][i] / dr / 5.0f;
            __syncthreads();
        }
        for (int i = tid; i < Nc; i += 256) {
            float cs = Q[0][i]+Q[1][i]+Q[2][i]+Q[3][i]+Q[4][i];
            float dc = (cs > 0.0f) ? cs : 1.0f;
            #pragma unroll
            for (int k = 0; k < KP; k++) Q[k][i] = Q[k][i] / dc / fNc;
        }
        __syncthreads();
    }
    for (int k = 0; k < KP; k++)
        for (int i = tid; i < Nc; i += 256) Q[k][i] *= fNc;
    __syncthreads();

    for (int i = tid; i < Nc; i += 256) {
        float best = Q[0][i]; int ba = 0;
        #pragma unroll
        for (int k = 1; k < KP; k++) if (Q[k][i] > best) { best = Q[k][i]; ba = k; }
        assign[s_idx[i]] = (float)(c*KP + ba);
    }

    const int d0 = tid * 3;
    float acc[KP][3];
    #pragma unroll
    for (int k = 0; k < KP; k++) { acc[k][0]=0.f; acc[k][1]=0.f; acc[k][2]=0.f; }
    for (int i = 0; i < Nc; i++) {
        const float* xp = g_rpt + (size_t)s_idx[i]*DD + d0;
        float x0 = xp[0], x1 = xp[1], x2 = xp[2];
        #pragma unroll
        for (int k = 0; k < KP; k++) {
            float q = Q[k][i];
            acc[k][0] = fmaf(q, x0, acc[k][0]);
            acc[k][1] = fmaf(q, x1, acc[k][1]);
            acc[k][2] = fmaf(q, x2, acc[k][2]);
        }
    }
    const float g = 0.999f, og = 1.0f - 0.999f;
    #pragma unroll
    for (int k = 0; k < KP; k++) {
        size_t basep = ((size_t)c*KP + k)*DD + d0;
        #pragma unroll
        for (int j = 0; j < 3; j++)
            pnew[basep + j] = g * proto[basep + j] + og * acc[k][j];
    }
}

// ---------------------------------------------------------------------------
extern "C" void kernel_launch(void* const* d_in, const int* in_sizes, int n_in,
                              void* d_out, int out_size) {
    const float* pt    = (const float*)d_in[0];
    const float* rpt   = (const float*)d_in[1];
    const float* proto = (const float*)d_in[2];
    const float* sa    = (const float*)d_in[3];
    const int*   lbl   = (const int*)  d_in[4];
    float* out = (float*)d_out;

    cudaFuncSetAttribute(gemm_mma_kernel,
                         cudaFuncAttributeMaxDynamicSharedMemorySize, SMEM_GEMM);

    norm_kernel<<<(2*NN + JPAD + 7)/8, 256>>>(pt, rpt, proto);
    sw_kernel<<<1, 256>>>(sa);
    {
        dim3 grid(NN/128, JPAD/128);   // 98 x 8
        gemm_mma_kernel<<<grid, 256, SMEM_GEMM>>>(out + OFF_LOGITS);
    }
    imgmax_kernel<<<(BB*JJ + 255)/256, 256>>>(out + OFF_LOGITS, out + OFF_IMG);
    cls_kernel<<<(BB*NCLS + 255)/256, 256>>>(out + OFF_IMG, out + OFF_CLS);
    sinkhorn_kernel<<<CC, 256>>>(out + OFF_LOGITS, lbl, proto,
                                 out + OFF_ASGN, out + OFF_PNEW);
}

// round 6
// speedup vs baseline: 2.0393x; 1.0749x over previous
#include <cuda_runtime.h>
#include <cuda_fp16.h>
#include <cstdint>
#include <math.h>

// Problem constants
#define BB 64
#define PP 196
#define DD 768
#define CC 201
#define KP 5
#define NCLS 200
#define NN (BB*PP)        // 12544
#define JJ (CC*KP)        // 1005
#define JPAD 1024

// Output layout (float32, concatenated in reference return order)
#define OFF_LOGITS 0
#define SZ_LOGITS  (NN*JJ)
#define OFF_IMG    (OFF_LOGITS + SZ_LOGITS)
#define SZ_IMG     (BB*JJ)
#define OFF_CLS    (OFF_IMG + SZ_IMG)
#define SZ_CLS     (BB*NCLS)
#define OFF_ASGN   (OFF_CLS + SZ_CLS)
#define SZ_ASGN    (NN)
#define OFF_PNEW   (OFF_ASGN + SZ_ASGN)
#define SZ_PNEW    (CC*KP*DD)

// Device scratch
__device__ __align__(16) __half g_pth[NN*DD];     // fp16(A)        (normalized pt)
__device__ __align__(16) __half g_pt2[NN*DD];     // fp16(Ah+64*Al)
__device__ __align__(16) __half g_pnh[JPAD*DD];   // fp16(B)        (normalized protos)
__device__ __align__(16) __half g_pn2[JPAD*DD];   // fp16(Bh+64*Bl)
__device__ float g_inv[NN];                       // 1/||rpt_row||
__device__ float g_sw[NCLS*KP];

// ---------------------------------------------------------------------------
// PTX helpers
// ---------------------------------------------------------------------------
__device__ __forceinline__ void ldsm_x4(uint32_t* r, uint32_t addr) {
    asm volatile("ldmatrix.sync.aligned.m8n8.x4.shared.b16 {%0,%1,%2,%3}, [%4];"
                 : "=r"(r[0]), "=r"(r[1]), "=r"(r[2]), "=r"(r[3]) : "r"(addr));
}
__device__ __forceinline__ void mma_fp16(float* d, const uint32_t* a, const uint32_t* b) {
    asm volatile(
        "mma.sync.aligned.m16n8k16.row.col.f32.f16.f16.f32 "
        "{%0,%1,%2,%3}, {%4,%5,%6,%7}, {%8,%9}, {%0,%1,%2,%3};"
        : "+f"(d[0]), "+f"(d[1]), "+f"(d[2]), "+f"(d[3])
        : "r"(a[0]), "r"(a[1]), "r"(a[2]), "r"(a[3]), "r"(b[0]), "r"(b[1]));
}
__device__ __forceinline__ void cpa16(uint32_t smem, const void* g) {
    asm volatile("cp.async.ca.shared.global [%0], [%1], 16;" :: "r"(smem), "l"(g));
}
__device__ __forceinline__ void cpa_commit() {
    asm volatile("cp.async.commit_group;" ::: "memory");
}
template <int N>
__device__ __forceinline__ void cpa_wait() {
    asm volatile("cp.async.wait_group %0;" :: "n"(N) : "memory");
}

// ---------------------------------------------------------------------------
// Row L2 normalization + fp16 Ootomo split (warp per row)
// rows [0,NN): pt -> g_pth/g_pt2 ; [NN,2NN): rpt -> g_inv only ;
// [2NN,2NN+JPAD): protos -> g_pnh/g_pn2 (pad rows zero)
// ---------------------------------------------------------------------------
__global__ __launch_bounds__(256) void norm_kernel(const float* __restrict__ pt,
                            const float* __restrict__ rpt,
                            const float* __restrict__ proto) {
    const int r = blockIdx.x * 8 + (threadIdx.x >> 5);
    const int lane = threadIdx.x & 31;
    if (r >= 2*NN + JPAD) return;

    if (r < NN) {
        const float* src = pt + (size_t)r*DD;
        float s = 0.0f;
        for (int i = lane; i < DD; i += 32) { float v = src[i]; s += v*v; }
        #pragma unroll
        for (int o = 16; o > 0; o >>= 1) s += __shfl_xor_sync(0xffffffffu, s, o);
        float inv = 1.0f / fmaxf(sqrtf(s), 1e-12f);
        for (int i = lane; i < DD; i += 32) {
            float x = src[i] * inv;
            __half h = __float2half(x);
            float hf = __half2float(h);
            g_pth[(size_t)r*DD + i] = h;
            g_pt2[(size_t)r*DD + i] = __float2half(fmaf(64.0f, x - hf, hf));
        }
    } else if (r < 2*NN) {
        int rr = r - NN;
        const float* src = rpt + (size_t)rr*DD;
        float s = 0.0f;
        for (int i = lane; i < DD; i += 32) { float v = src[i]; s += v*v; }
        #pragma unroll
        for (int o = 16; o > 0; o >>= 1) s += __shfl_xor_sync(0xffffffffu, s, o);
        if (lane == 0) g_inv[rr] = 1.0f / fmaxf(sqrtf(s), 1e-12f);
    } else {
        int j = r - 2*NN;
        if (j >= JJ) {
            __half z = __float2half(0.0f);
            for (int i = lane; i < DD; i += 32) {
                g_pnh[(size_t)j*DD + i] = z;
                g_pn2[(size_t)j*DD + i] = z;
            }
            return;
        }
        const float* src = proto + (size_t)j*DD;
        float s = 0.0f;
        for (int i = lane; i < DD; i += 32) { float v = src[i]; s += v*v; }
        #pragma unroll
        for (int o = 16; o > 0; o >>= 1) s += __shfl_xor_sync(0xffffffffu, s, o);
        float inv = 1.0f / fmaxf(sqrtf(s), 1e-12f);
        for (int i = lane; i < DD; i += 32) {
            float x = src[i] * inv;
            __half h = __float2half(x);
            float hf = __half2float(h);
            g_pnh[(size_t)j*DD + i] = h;
            g_pn2[(size_t)j*DD + i] = __float2half(fmaf(64.0f, x - hf, hf));
        }
    }
}

// ---------------------------------------------------------------------------
// sw = softmax(sa_weights, axis=-1) * K
// ---------------------------------------------------------------------------
__global__ void sw_kernel(const float* __restrict__ sa) {
    int c = blockIdx.x * blockDim.x + threadIdx.x;
    if (c >= NCLS) return;
    float w[KP];
    float m = -1e30f;
    for (int k = 0; k < KP; k++) { w[k] = sa[c*KP+k]; m = fmaxf(m, w[k]); }
    float s = 0.0f;
    for (int k = 0; k < KP; k++) { w[k] = expf(w[k]-m); s += w[k]; }
    for (int k = 0; k < KP; k++) g_sw[c*KP+k] = w[k] / s * 5.0f;
}

// ---------------------------------------------------------------------------
// 2-product fp16 GEMM (Ootomo):  out = P0 + (P1 - P0)/64
// CTA 128x64, BK=32, 8 warps (4M x 2N), warp tile 32x32, 2-stage cp.async
// ---------------------------------------------------------------------------
#define SAS 40                               // smem row stride (fp16 elems)
#define A_TB (128*SAS*2)                     // 10240 bytes per A array
#define B_TB (64*SAS*2)                      // 5120 bytes per B array
#define STAGE_B (2*A_TB + 2*B_TB)            // 30720 bytes per stage
#define SMEM_GEMM (2*STAGE_B)                // 61440
#define NCHUNK (DD/32)                       // 24
// within stage: Ah @0, A2 @A_TB, Bh @2*A_TB, B2 @2*A_TB+B_TB

__global__ __launch_bounds__(256, 2) void gemm_mma_kernel(float* __restrict__ out) {
    extern __shared__ __align__(16) char smem[];
    const uint32_t sb = (uint32_t)__cvta_generic_to_shared(smem);

    const int tid  = threadIdx.x;
    const int lane = tid & 31;
    const int wid  = tid >> 5;
    const int wm   = wid & 3;      // M 32-block
    const int wn   = wid >> 2;     // N 32-block
    const int bm   = blockIdx.x * 128;
    const int bn   = blockIdx.y * 64;

    const int arow = (lane & 7) + ((lane >> 3) & 1) * 8;
    const int acol = (lane >> 4) * 8;
    const int brow = (lane & 7) + ((lane >> 4) & 1) * 8;
    const int bcol = ((lane >> 3) & 1) * 8;

    float acc0[2][4][4], acc1[2][4][4];
    #pragma unroll
    for (int i = 0; i < 2; i++)
        #pragma unroll
        for (int j = 0; j < 4; j++)
            #pragma unroll
            for (int q = 0; q < 4; q++) { acc0[i][j][q] = 0.0f; acc1[i][j][q] = 0.0f; }

    const int gr0 = tid >> 2;          // 0..63
    const int gq0 = tid & 3;           // 16B chunk (of 4 per 32-elem row)

    auto load_chunk = [&](int kt, int s) {
        uint32_t st = sb + s*STAGE_B;
        // A: rows gr0 and gr0+64
        #pragma unroll
        for (int l = 0; l < 2; l++) {
            int row = gr0 + l*64;
            uint32_t so = (uint32_t)(row*SAS + gq0*8) * 2;
            size_t gi = (size_t)(bm + row)*DD + kt + gq0*8;
            cpa16(st + so,        g_pth + gi);
            cpa16(st + A_TB + so, g_pt2 + gi);
        }
        // B: row gr0
        {
            uint32_t so = (uint32_t)(gr0*SAS + gq0*8) * 2;
            size_t gj = (size_t)(bn + gr0)*DD + kt + gq0*8;
            cpa16(st + 2*A_TB + so,        g_pnh + gj);
            cpa16(st + 2*A_TB + B_TB + so, g_pn2 + gj);
        }
        cpa_commit();
    };

    load_chunk(0, 0);

    for (int i = 0; i < NCHUNK; i++) {
        const int s = i & 1;
        if (i + 1 < NCHUNK) {
            load_chunk((i+1)*32, (i+1) & 1);
            cpa_wait<1>();
        } else {
            cpa_wait<0>();
        }
        __syncthreads();

        const uint32_t aAh = sb + s*STAGE_B;
        const uint32_t aA2 = aAh + A_TB;
        const uint32_t aBh = aAh + 2*A_TB;
        const uint32_t aB2 = aBh + B_TB;

        #pragma unroll
        for (int ks = 0; ks < 32; ks += 16) {
            uint32_t ah[2][4], a2[2][4];
            #pragma unroll
            for (int mi = 0; mi < 2; mi++) {
                uint32_t off = (uint32_t)((wm*32 + mi*16 + arow)*SAS + ks + acol) * 2;
                ldsm_x4(ah[mi], aAh + off);
                ldsm_x4(a2[mi], aA2 + off);
            }
            #pragma unroll
            for (int nb = 0; nb < 2; nb++) {
                uint32_t bh[4], b2[4];
                uint32_t off = (uint32_t)((wn*32 + nb*16 + brow)*SAS + ks + bcol) * 2;
                ldsm_x4(bh, aBh + off);
                ldsm_x4(b2, aB2 + off);
                #pragma unroll
                for (int mi = 0; mi < 2; mi++) {
                    mma_fp16(acc0[mi][nb*2+0], ah[mi], bh+0);
                    mma_fp16(acc0[mi][nb*2+1], ah[mi], bh+2);
                    mma_fp16(acc1[mi][nb*2+0], a2[mi], b2+0);
                    mma_fp16(acc1[mi][nb*2+1], a2[mi], b2+2);
                }
            }
        }
        __syncthreads();
    }

    // epilogue: combine P0 + (P1-P0)/64, scalar fp32 stores (JJ odd)
    #pragma unroll
    for (int mi = 0; mi < 2; mi++) {
        #pragma unroll
        for (int nf = 0; nf < 4; nf++) {
            int col = bn + wn*32 + nf*8 + (lane & 3)*2;
            #pragma unroll
            for (int h = 0; h < 2; h++) {
                int row = bm + wm*32 + mi*16 + (lane >> 2) + h*8;
                size_t base = (size_t)row*JJ + col;
                float p0a = acc0[mi][nf][h*2+0], p1a = acc1[mi][nf][h*2+0];
                float p0b = acc0[mi][nf][h*2+1], p1b = acc1[mi][nf][h*2+1];
                float va = p0a + (p1a - p0a) * 0.015625f;
                float vb = p0b + (p1b - p0b) * 0.015625f;
                if (col < JJ)     out[base]     = va;
                if (col + 1 < JJ) out[base + 1] = vb;
            }
        }
    }
}

// ---------------------------------------------------------------------------
// image_logits[b, j] = max_p logits[b, p, j]
// ---------------------------------------------------------------------------
__global__ void imgmax_kernel(const float* __restrict__ logits, float* __restrict__ img) {
    int t = blockIdx.x * blockDim.x + threadIdx.x;
    if (t >= BB*JJ) return;
    int b = t / JJ, j = t % JJ;
    const float* p = logits + (size_t)b*PP*JJ + j;
    float m = -1e30f;
    for (int i = 0; i < PP; i++) m = fmaxf(m, p[(size_t)i*JJ]);
    img[(size_t)b*JJ + j] = m;
}

// ---------------------------------------------------------------------------
// class_logits[b, c] = sum_k img[b, c, k]*sw[c, k] / TEMP
// ---------------------------------------------------------------------------
__global__ void cls_kernel(const float* __restrict__ img, float* __restrict__ cls) {
    int t = blockIdx.x * blockDim.x + threadIdx.x;
    if (t >= BB*NCLS) return;
    int b = t / NCLS, c = t % NCLS;
    float s = 0.0f;
    #pragma unroll
    for (int k = 0; k < KP; k++) s += img[(size_t)b*JJ + c*KP + k] * g_sw[c*KP+k];
    cls[t] = s / 0.2f;
}

// ---------------------------------------------------------------------------
// Per-class: deterministic compaction + Sinkhorn + assignment + P_new
// (uses raw rpt scaled by g_inv folded into Q)
// ---------------------------------------------------------------------------
#define MAXN 1024
__global__ __launch_bounds__(256) void sinkhorn_kernel(
        const float* __restrict__ logits, const int* __restrict__ labels,
        const float* __restrict__ proto, const float* __restrict__ rpt,
        float* __restrict__ assign, float* __restrict__ pnew) {
    const int c = blockIdx.x;
    const int tid = threadIdx.x;
    const int lane = tid & 31, w = tid >> 5;

    __shared__ int   s_idx[MAXN];
    __shared__ float Q[KP][MAXN];
    __shared__ float red[256];
    __shared__ int   warp_cnt[8], warp_off[8];
    __shared__ int   s_n;

    if (tid == 0) s_n = 0;
    __syncthreads();

    for (int base = 0; base < NN; base += 256) {
        int n = base + tid;
        bool p = (labels[n] == c);
        unsigned bal = __ballot_sync(0xffffffffu, p);
        if (lane == 0) warp_cnt[w] = __popc(bal);
        __syncthreads();
        if (tid == 0) {
            int s = s_n;
            #pragma unroll
            for (int i = 0; i < 8; i++) { warp_off[i] = s; s += warp_cnt[i]; }
            s_n = s;
        }
        __syncthreads();
        if (p) {
            int pos = warp_off[w] + __popc(bal & ((1u << lane) - 1u));
            if (pos < MAXN) s_idx[pos] = n;
        }
        __syncthreads();
    }
    const int Nc = min(s_n, MAXN);

    if (Nc == 0) {
        for (int x = tid; x < KP*DD; x += 256)
            pnew[(size_t)c*KP*DD + x] = proto[(size_t)c*KP*DD + x];
        return;
    }

    for (int i = tid; i < Nc; i += 256) {
        const float* lp = logits + (size_t)s_idx[i]*JJ + c*KP;
        #pragma unroll
        for (int k = 0; k < KP; k++) Q[k][i] = expf(lp[k] * 20.0f);
    }
    __syncthreads();

    float s = 0.0f;
    for (int k = 0; k < KP; k++)
        for (int i = tid; i < Nc; i += 256) s += Q[k][i];
    red[tid] = s; __syncthreads();
    for (int o = 128; o > 0; o >>= 1) { if (tid < o) red[tid] += red[tid+o]; __syncthreads(); }
    float tot = red[0];
    __syncthreads();
    float dTot = (tot > 0.0f) ? tot : 1.0f;
    for (int k = 0; k < KP; k++)
        for (int i = tid; i < Nc; i += 256) Q[k][i] /= dTot;
    __syncthreads();

    const float fNc = (float)Nc;
    for (int it = 0; it < 3; it++) {
        for (int k = 0; k < KP; k++) {
            float rs = 0.0f;
            for (int i = tid; i < Nc; i += 256) rs += Q[k][i];
            red[tid] = rs; __syncthreads();
            for (int o = 128; o > 0; o >>= 1) { if (tid < o) red[tid] += red[tid+o]; __syncthreads(); }
            float r = red[0];
            __syncthreads();
            float dr = (r > 0.0f) ? r : 1.0f;
            for (int i = tid; i < Nc; i += 256) Q[k][i] = Q[k][i] / dr / 5.0f;
            __syncthreads();
        }
        for (int i = tid; i < Nc; i += 256) {
            float cs = Q[0][i]+Q[1][i]+Q[2][i]+Q[3][i]+Q[4][i];
            float dc = (cs > 0.0f) ? cs : 1.0f;
            #pragma unroll
            for (int k = 0; k < KP; k++) Q[k][i] = Q[k][i] / dc / fNc;
        }
        __syncthreads();
    }
    for (int k = 0; k < KP; k++)
        for (int i = tid; i < Nc; i += 256) Q[k][i] *= fNc;
    __syncthreads();

    for (int i = tid; i < Nc; i += 256) {
        float best = Q[0][i]; int ba = 0;
        #pragma unroll
        for (int k = 1; k < KP; k++) if (Q[k][i] > best) { best = Q[k][i]; ba = k; }
        assign[s_idx[i]] = (float)(c*KP + ba);
    }
    __syncthreads();

    // fold row inverse-norm into Q (patches_flat = rpt_row * inv)
    for (int i = tid; i < Nc; i += 256) {
        float inv = g_inv[s_idx[i]];
        #pragma unroll
        for (int k = 0; k < KP; k++) Q[k][i] *= inv;
    }
    __syncthreads();

    const int d0 = tid * 3;
    float acc[KP][3];
    #pragma unroll
    for (int k = 0; k < KP; k++) { acc[k][0]=0.f; acc[k][1]=0.f; acc[k][2]=0.f; }
    for (int i = 0; i < Nc; i++) {
        const float* xp = rpt + (size_t)s_idx[i]*DD + d0;
        float x0 = xp[0], x1 = xp[1], x2 = xp[2];
        #pragma unroll
        for (int k = 0; k < KP; k++) {
            float q = Q[k][i];
            acc[k][0] = fmaf(q, x0, acc[k][0]);
            acc[k][1] = fmaf(q, x1, acc[k][1]);
            acc[k][2] = fmaf(q, x2, acc[k][2]);
        }
    }
    const float g = 0.999f, og = 1.0f - 0.999f;
    #pragma unroll
    for (int k = 0; k < KP; k++) {
        size_t basep = ((size_t)c*KP + k)*DD + d0;
        #pragma unroll
        for (int j = 0; j < 3; j++)
            pnew[basep + j] = g * proto[basep + j] + og * acc[k][j];
    }
}

// ---------------------------------------------------------------------------
extern "C" void kernel_launch(void* const* d_in, const int* in_sizes, int n_in,
                              void* d_out, int out_size) {
    const float* pt    = (const float*)d_in[0];
    const float* rpt   = (const float*)d_in[1];
    const float* proto = (const float*)d_in[2];
    const float* sa    = (const float*)d_in[3];
    const int*   lbl   = (const int*)  d_in[4];
    float* out = (float*)d_out;

    cudaFuncSetAttribute(gemm_mma_kernel,
                         cudaFuncAttributeMaxDynamicSharedMemorySize, SMEM_GEMM);

    norm_kernel<<<(2*NN + JPAD + 7)/8, 256>>>(pt, rpt, proto);
    sw_kernel<<<1, 256>>>(sa);
    {
        dim3 grid(NN/128, JPAD/64);   // 98 x 16
        gemm_mma_kernel<<<grid, 256, SMEM_GEMM>>>(out + OFF_LOGITS);
    }
    imgmax_kernel<<<(BB*JJ + 255)/256, 256>>>(out + OFF_LOGITS, out + OFF_IMG);
    cls_kernel<<<(BB*NCLS + 255)/256, 256>>>(out + OFF_IMG, out + OFF_CLS);
    sinkhorn_kernel<<<CC, 256>>>(out + OFF_LOGITS, lbl, proto, rpt,
                                 out + OFF_ASGN, out + OFF_PNEW);
}